// round 6
// baseline (speedup 1.0000x reference)
#include <cuda_runtime.h>
#include <cuda_bf16.h>
#include <cstdint>

// ---------------- problem dims ----------------
#define B_SZ   1024
#define S_SZ   256
#define IN_SZ  8
#define H_SZ   512
#define F_SZ   96
#define G4     2048          // 4*H
#define KV     1536          // virtual K: [hi | hi | lo] x [Whi | Wlo | Whi]
#define NCHUNK 24            // KV / 64
#define NCTA_N 16
#define NCTA_M 8

// ---------------- shared memory layout ----------------
// 4 stages x (A 16 KB + B 16 KB); epilogue reuses stage region as C (128x132 f32)
#define STAGE_BYTES 32768
#define SM_BIAS   131072
#define SM_WIH    131584
#define SM_XS     135680
#define SM_OUTW   140288
#define SMEM_TOTAL 140416

// ---------------- static device scratch (no runtime alloc) ----------------
__device__ __align__(1024) __nv_bfloat16 g_Wv[3][(size_t)G4 * KV];   // enc / dec0 / dec-folded
__device__ __align__(1024) __nv_bfloat16 g_A[2][(size_t)B_SZ * KV];  // ping-pong A_virt
__device__ __align__(1024) float g_Cst[B_SZ * H_SZ];                 // cell state fp32
__device__ float g_bias[3][G4];                                      // permuted fused biases
__device__ float g_WihP[G4 * IN_SZ];                                 // permuted enc_Wih
__device__ float g_predP[F_SZ][NCTA_N][B_SZ];                        // per-nCTA pred partials

// ---------------- helpers ----------------
__device__ __forceinline__ uint32_t smem_u32(const void* p) {
    uint32_t a;
    asm("{ .reg .u64 t; cvta.to.shared.u64 t, %1; cvt.u32.u64 %0, t; }" : "=r"(a) : "l"(p));
    return a;
}
__device__ __forceinline__ void cp16(uint32_t saddr, const void* gptr) {
    asm volatile("cp.async.cg.shared.global [%0], [%1], 16;"
                 :: "r"(saddr), "l"(__cvta_generic_to_global(gptr)) : "memory");
}
#define CP_COMMIT() asm volatile("cp.async.commit_group;" ::: "memory")
#define CP_WAIT2()  asm volatile("cp.async.wait_group 2;" ::: "memory")

__device__ __forceinline__ void ldm4(uint32_t& r0, uint32_t& r1, uint32_t& r2, uint32_t& r3,
                                     uint32_t addr) {
    asm volatile("ldmatrix.sync.aligned.m8n8.x4.shared.b16 {%0,%1,%2,%3}, [%4];"
                 : "=r"(r0), "=r"(r1), "=r"(r2), "=r"(r3) : "r"(addr));
}
__device__ __forceinline__ void mma16816(float* c, const uint32_t* a, const uint32_t* b) {
    asm volatile(
        "mma.sync.aligned.m16n8k16.row.col.f32.bf16.bf16.f32 "
        "{%0,%1,%2,%3}, {%4,%5,%6,%7}, {%8,%9}, {%0,%1,%2,%3};"
        : "+f"(c[0]), "+f"(c[1]), "+f"(c[2]), "+f"(c[3])
        : "r"(a[0]), "r"(a[1]), "r"(a[2]), "r"(a[3]), "r"(b[0]), "r"(b[1]));
}

// ---------------- prep: permute + hi/lo split weights, fold decoder feedback ----------------
// permuted col p = 4u + gate  <-  source row s = gate*512 + u  (PyTorch gate order i,f,g,o)
__global__ void prep_kernel(const float* __restrict__ encWhh, const float* __restrict__ decWhh,
                            const float* __restrict__ decWih, const float* __restrict__ outW,
                            const float* __restrict__ encBih, const float* __restrict__ encBhh,
                            const float* __restrict__ decBih, const float* __restrict__ decBhh,
                            const float* __restrict__ outB,   const float* __restrict__ encWih) {
    int idx = blockIdx.x * blockDim.x + threadIdx.x;
    if (idx < G4 * H_SZ) {
        int p = idx >> 9;
        int k = idx & 511;
        int s = ((p & 3) << 9) | (p >> 2);
        size_t o = (size_t)p * KV + k;

        float v0 = encWhh[s * H_SZ + k];
        __nv_bfloat16 h0 = __float2bfloat16(v0);
        __nv_bfloat16 l0 = __float2bfloat16(v0 - __bfloat162float(h0));
        g_Wv[0][o] = h0; g_Wv[0][o + 512] = l0; g_Wv[0][o + 1024] = h0;

        float v1 = decWhh[s * H_SZ + k];
        __nv_bfloat16 h1 = __float2bfloat16(v1);
        __nv_bfloat16 l1 = __float2bfloat16(v1 - __bfloat162float(h1));
        g_Wv[1][o] = h1; g_Wv[1][o + 512] = l1; g_Wv[1][o + 1024] = h1;

        float v2 = v1 + decWih[s] * outW[k];           // fold y-feedback into Whh
        __nv_bfloat16 h2 = __float2bfloat16(v2);
        __nv_bfloat16 l2 = __float2bfloat16(v2 - __bfloat162float(h2));
        g_Wv[2][o] = h2; g_Wv[2][o + 512] = l2; g_Wv[2][o + 1024] = h2;
    }
    if (idx < G4) {
        int p = idx;
        int s = ((p & 3) << 9) | (p >> 2);
        g_bias[0][p] = encBih[s] + encBhh[s];
        float db = decBih[s] + decBhh[s];
        g_bias[1][p] = db;
        g_bias[2][p] = db + outB[0] * decWih[s];       // fold outB feedback
#pragma unroll
        for (int j = 0; j < IN_SZ; j++) g_WihP[p * IN_SZ + j] = encWih[s * IN_SZ + j];
    }
}

__global__ void init_kernel() {
    int i = blockIdx.x * blockDim.x + threadIdx.x;
    int stride = gridDim.x * blockDim.x;
    uint32_t* a0 = reinterpret_cast<uint32_t*>(g_A[0]);
    for (int idx = i; idx < B_SZ * KV / 2; idx += stride) a0[idx] = 0u;
    for (int idx = i; idx < B_SZ * H_SZ; idx += stride) g_Cst[idx] = 0.f;
}

// ---------------- one LSTM time step ----------------
// C[128x128 tile] = A_virt[1024x1536] x B_virt[2048x1536]^T, then gate math locally.
// grid (16, 8): blockIdx.x = N-tile (128 permuted gate cols = 32 units), blockIdx.y = M-tile
__global__ void __launch_bounds__(256, 1)
step_kernel(int wsel, int pb, int t_x, int td,
            const float* __restrict__ x, const float* __restrict__ outW) {
    extern __shared__ char smem[];
    const uint32_t sb = smem_u32(smem);
    const int tid = threadIdx.x;
    const int n0 = blockIdx.x, m0 = blockIdx.y;
    const bool has_x = (t_x >= 0);

    // ---- epilogue constants into their own smem region ----
    float* sm_bias = (float*)(smem + SM_BIAS);
    float* sm_wih  = (float*)(smem + SM_WIH);
    float* sm_xs   = (float*)(smem + SM_XS);
    float* sm_outw = (float*)(smem + SM_OUTW);
    if (tid < 128) sm_bias[tid] = g_bias[wsel][n0 * 128 + tid];
    if (tid < 32)  sm_outw[tid] = outW[n0 * 32 + tid];
    if (has_x) {
        for (int i = tid; i < 128 * IN_SZ; i += 256) {
            sm_wih[i] = g_WihP[n0 * 128 * IN_SZ + i];
            int r = i >> 3, j = i & 7;
            sm_xs[r * 9 + j] = x[((size_t)(m0 * 128 + r) * S_SZ + t_x) * IN_SZ + j];
        }
    }

    const __nv_bfloat16* __restrict__ gA = g_A[pb] + (size_t)m0 * 128 * KV;
    const __nv_bfloat16* __restrict__ gB = g_Wv[wsel] + (size_t)n0 * 128 * KV;

    // ---- stage loader: global -> XOR-swizzled smem via cp.async ----
    auto load_stage = [&](int kc, int slot) {
        const uint32_t stA = sb + slot * STAGE_BYTES;
        const uint32_t stB = stA + 16384;
        const int c16 = tid & 7;
        const int rb = tid >> 3;
#pragma unroll
        for (int it = 0; it < 4; it++) {
            int r = rb + it * 32;
            uint32_t so = (uint32_t)(r * 128 + ((c16 ^ (r & 7)) << 4));
            cp16(stA + so, gA + (size_t)r * KV + kc * 64 + c16 * 8);
            cp16(stB + so, gB + (size_t)r * KV + kc * 64 + c16 * 8);
        }
    };

    load_stage(0, 0); CP_COMMIT();
    load_stage(1, 1); CP_COMMIT();
    load_stage(2, 2); CP_COMMIT();

    const int lane = tid & 31, w = tid >> 5;
    const int wm = w & 1, wn = w >> 1;        // warp tile: 64m x 32n
    const int lrow = lane & 15, lhalf = lane >> 4;

    float acc[4][4][4];
#pragma unroll
    for (int a = 0; a < 4; a++)
#pragma unroll
        for (int b = 0; b < 4; b++)
#pragma unroll
            for (int c = 0; c < 4; c++) acc[a][b][c] = 0.f;

    // ---- mainloop: 24 chunks of K=64, 4-stage cp.async pipeline ----
    for (int kc = 0; kc < NCHUNK; kc++) {
        CP_WAIT2();
        __syncthreads();
        const uint32_t stA = sb + (kc & 3) * STAGE_BYTES;
        const uint32_t stB = stA + 16384;
#pragma unroll
        for (int kk = 0; kk < 4; kk++) {
            uint32_t af[4][4];
#pragma unroll
            for (int mt = 0; mt < 4; mt++) {
                int r = wm * 64 + mt * 16 + lrow;
                int c16 = 2 * kk + lhalf;
                ldm4(af[mt][0], af[mt][1], af[mt][2], af[mt][3],
                     stA + r * 128 + ((c16 ^ (r & 7)) << 4));
            }
            uint32_t bfr[4][2];
#pragma unroll
            for (int nb = 0; nb < 2; nb++) {
                int r = wn * 32 + nb * 16 + lrow;
                int c16 = 2 * kk + lhalf;
                uint32_t r0, r1, r2, r3;
                ldm4(r0, r1, r2, r3, stB + r * 128 + ((c16 ^ (r & 7)) << 4));
                bfr[nb * 2 + 0][0] = r0; bfr[nb * 2 + 0][1] = r2;
                bfr[nb * 2 + 1][0] = r1; bfr[nb * 2 + 1][1] = r3;
            }
#pragma unroll
            for (int mt = 0; mt < 4; mt++)
#pragma unroll
                for (int nt = 0; nt < 4; nt++)
                    mma16816(acc[mt][nt], af[mt], bfr[nt]);
        }
        if (kc + 3 < NCHUNK) load_stage(kc + 3, (kc + 3) & 3);
        CP_COMMIT();   // unconditional: keeps wait_group 2 semantics at the tail
    }

    // ---- spill accum tile to smem (reuse stage region), stride 132 for aligned float4 ----
    __syncthreads();
    float* Cs = reinterpret_cast<float*>(smem);
#pragma unroll
    for (int mt = 0; mt < 4; mt++) {
#pragma unroll
        for (int nt = 0; nt < 4; nt++) {
            int r = wm * 64 + mt * 16 + (lane >> 2);
            int c = wn * 32 + nt * 8 + 2 * (lane & 3);
            Cs[r * 132 + c]           = acc[mt][nt][0];
            Cs[r * 132 + c + 1]       = acc[mt][nt][1];
            Cs[(r + 8) * 132 + c]     = acc[mt][nt][2];
            Cs[(r + 8) * 132 + c + 1] = acc[mt][nt][3];
        }
    }
    __syncthreads();

    // ---- gate pass: lane = local unit (cols 4u..4u+3 = i,f,g,o), 8 warps x 16 rows ----
    const int u = lane;
    const int ug = n0 * 32 + u;
    float wih[4][8];
    if (has_x) {
#pragma unroll
        for (int q = 0; q < 4; q++)
#pragma unroll
            for (int k = 0; k < 8; k++) wih[q][k] = sm_wih[(4 * u + q) * 8 + k];
    }
    const float b_i = sm_bias[4 * u], b_f = sm_bias[4 * u + 1];
    const float b_g = sm_bias[4 * u + 2], b_o = sm_bias[4 * u + 3];
    const float ow = sm_outw[u];
    __nv_bfloat16* __restrict__ hout = g_A[pb ^ 1];
    const int wrow = tid >> 5;

#pragma unroll 4
    for (int i = 0; i < 16; i++) {
        int r = wrow + i * 8;
        int grow = m0 * 128 + r;
        const float4 g4v = *reinterpret_cast<const float4*>(&Cs[r * 132 + 4 * u]);
        float gi = g4v.x + b_i, gf = g4v.y + b_f, gg = g4v.z + b_g, go = g4v.w + b_o;
        if (has_x) {
#pragma unroll
            for (int k = 0; k < 8; k++) {
                float xv = sm_xs[r * 9 + k];
                gi += xv * wih[0][k]; gf += xv * wih[1][k];
                gg += xv * wih[2][k]; go += xv * wih[3][k];
            }
        }
        float iv = 1.f / (1.f + expf(-gi));
        float fv = 1.f / (1.f + expf(-gf));
        float gv = tanhf(gg);
        float ov = 1.f / (1.f + expf(-go));
        size_t ci = (size_t)grow * H_SZ + ug;
        float cn = fv * g_Cst[ci] + iv * gv;
        g_Cst[ci] = cn;
        float hv = ov * tanhf(cn);
        __nv_bfloat16 hh = __float2bfloat16(hv);
        __nv_bfloat16 hl = __float2bfloat16(hv - __bfloat162float(hh));
        __nv_bfloat16* rowp = hout + (size_t)grow * KV;
        rowp[ug] = hh; rowp[512 + ug] = hh; rowp[1024 + ug] = hl;   // [Ah | Ah | Al]
        if (td >= 0) {
            float p = hv * ow;
#pragma unroll
            for (int s = 16; s > 0; s >>= 1) p += __shfl_xor_sync(0xFFFFFFFFu, p, s);
            if (lane == 0) g_predP[td][n0][grow] = p;   // deterministic partial
        }
    }
}

// ---------------- output: out[b][f] = outB + sum_n predP[f][n][b] ----------------
__global__ void out_kernel(float* __restrict__ out, const float* __restrict__ outB) {
    int i = blockIdx.x * blockDim.x + threadIdx.x;
    if (i < B_SZ * F_SZ) {
        int b = i / F_SZ, f = i % F_SZ;
        float s = outB[0];
#pragma unroll
        for (int n = 0; n < NCTA_N; n++) s += g_predP[f][n][b];
        out[i] = s;
    }
}

// ---------------- launch ----------------
extern "C" void kernel_launch(void* const* d_in, const int* in_sizes, int n_in,
                              void* d_out, int out_size) {
    const float* x      = (const float*)d_in[0];
    const float* encWih = (const float*)d_in[1];
    const float* encWhh = (const float*)d_in[2];
    const float* encBih = (const float*)d_in[3];
    const float* encBhh = (const float*)d_in[4];
    const float* decWih = (const float*)d_in[5];
    const float* decWhh = (const float*)d_in[6];
    const float* decBih = (const float*)d_in[7];
    const float* decBhh = (const float*)d_in[8];
    const float* outW   = (const float*)d_in[9];
    const float* outB   = (const float*)d_in[10];

    cudaFuncSetAttribute(step_kernel, cudaFuncAttributeMaxDynamicSharedMemorySize, SMEM_TOTAL);

    init_kernel<<<512, 256>>>();
    prep_kernel<<<(G4 * H_SZ + 255) / 256, 256>>>(encWhh, decWhh, decWih, outW,
                                                  encBih, encBhh, decBih, decBhh, outB, encWih);
    dim3 grid(NCTA_N, NCTA_M);
    // encoder: 256 steps with x-term, weight set 0
    for (int t = 0; t < S_SZ; t++)
        step_kernel<<<grid, 256, SMEM_TOTAL>>>(0, t & 1, t, -1, x, outW);
    // decoder step 0: y0 = 0 -> plain dec weights (set 1)
    step_kernel<<<grid, 256, SMEM_TOTAL>>>(1, S_SZ & 1, -1, 0, x, outW);
    // decoder steps 1..95: feedback folded into weights (set 2)
    for (int t = 1; t < F_SZ; t++)
        step_kernel<<<grid, 256, SMEM_TOTAL>>>(2, (S_SZ + t) & 1, -1, t, x, outW);

    out_kernel<<<(B_SZ * F_SZ + 255) / 256, 256>>>((float*)d_out, outB);
}

// round 7
// speedup vs baseline: 1.0884x; 1.0884x over previous
#include <cuda_runtime.h>
#include <cuda_bf16.h>
#include <cstdint>

// ---------------- problem dims ----------------
#define B_SZ   1024
#define S_SZ   256
#define IN_SZ  8
#define H_SZ   512
#define F_SZ   96
#define G4     2048          // 4*H
#define KV     1536          // virtual K: [hi | hi | lo] x [Whi | Wlo | Whi]
#define NCHUNK 24            // KV / 64
#define NCTA_N 16
#define NCTA_M 8

// ---------------- shared memory layout ----------------
// 4 stages x (A 16 KB + B 16 KB); epilogue reuses stage region as C (128x132 f32)
#define STAGE_BYTES 32768
#define SM_BIAS   131072
#define SM_WIH    131584
#define SM_XS     135680
#define SM_OUTW   140288
#define SMEM_TOTAL 140416

// ---------------- static device scratch (no runtime alloc) ----------------
__device__ __align__(1024) __nv_bfloat16 g_Wv[3][(size_t)G4 * KV];   // enc / dec0 / dec-folded
__device__ __align__(1024) __nv_bfloat16 g_A[2][(size_t)B_SZ * KV];  // ping-pong A_virt
__device__ __align__(1024) float g_Cst[B_SZ * H_SZ];                 // cell state fp32
__device__ float g_bias[3][G4];                                      // permuted fused biases
__device__ float g_WihP[G4 * IN_SZ];                                 // permuted enc_Wih
__device__ float g_predP[F_SZ][NCTA_N][B_SZ];                        // per-nCTA pred partials

// ---------------- helpers ----------------
__device__ __forceinline__ uint32_t smem_u32(const void* p) {
    uint32_t a;
    asm("{ .reg .u64 t; cvta.to.shared.u64 t, %1; cvt.u32.u64 %0, t; }" : "=r"(a) : "l"(p));
    return a;
}
__device__ __forceinline__ void cp16(uint32_t saddr, const void* gptr) {
    asm volatile("cp.async.cg.shared.global [%0], [%1], 16;"
                 :: "r"(saddr), "l"(__cvta_generic_to_global(gptr)) : "memory");
}
#define CP_COMMIT() asm volatile("cp.async.commit_group;" ::: "memory")
#define CP_WAIT2()  asm volatile("cp.async.wait_group 2;" ::: "memory")

__device__ __forceinline__ void ldm4(uint32_t& r0, uint32_t& r1, uint32_t& r2, uint32_t& r3,
                                     uint32_t addr) {
    asm volatile("ldmatrix.sync.aligned.m8n8.x4.shared.b16 {%0,%1,%2,%3}, [%4];"
                 : "=r"(r0), "=r"(r1), "=r"(r2), "=r"(r3) : "r"(addr));
}
__device__ __forceinline__ void mma16816(float* c, const uint32_t* a, const uint32_t* b) {
    asm volatile(
        "mma.sync.aligned.m16n8k16.row.col.f32.bf16.bf16.f32 "
        "{%0,%1,%2,%3}, {%4,%5,%6,%7}, {%8,%9}, {%0,%1,%2,%3};"
        : "+f"(c[0]), "+f"(c[1]), "+f"(c[2]), "+f"(c[3])
        : "r"(a[0]), "r"(a[1]), "r"(a[2]), "r"(a[3]), "r"(b[0]), "r"(b[1]));
}

// ---------------- prep: permute + hi/lo split weights, fold decoder feedback ----------------
// permuted col p = 4u + gate  <-  source row s = gate*512 + u  (PyTorch gate order i,f,g,o)
__global__ void prep_kernel(const float* __restrict__ encWhh, const float* __restrict__ decWhh,
                            const float* __restrict__ decWih, const float* __restrict__ outW,
                            const float* __restrict__ encBih, const float* __restrict__ encBhh,
                            const float* __restrict__ decBih, const float* __restrict__ decBhh,
                            const float* __restrict__ outB,   const float* __restrict__ encWih) {
    int idx = blockIdx.x * blockDim.x + threadIdx.x;
    if (idx < G4 * H_SZ) {
        int p = idx >> 9;
        int k = idx & 511;
        int s = ((p & 3) << 9) | (p >> 2);
        size_t o = (size_t)p * KV + k;

        float v0 = encWhh[s * H_SZ + k];
        __nv_bfloat16 h0 = __float2bfloat16(v0);
        __nv_bfloat16 l0 = __float2bfloat16(v0 - __bfloat162float(h0));
        g_Wv[0][o] = h0; g_Wv[0][o + 512] = l0; g_Wv[0][o + 1024] = h0;

        float v1 = decWhh[s * H_SZ + k];
        __nv_bfloat16 h1 = __float2bfloat16(v1);
        __nv_bfloat16 l1 = __float2bfloat16(v1 - __bfloat162float(h1));
        g_Wv[1][o] = h1; g_Wv[1][o + 512] = l1; g_Wv[1][o + 1024] = h1;

        float v2 = v1 + decWih[s] * outW[k];           // fold y-feedback into Whh
        __nv_bfloat16 h2 = __float2bfloat16(v2);
        __nv_bfloat16 l2 = __float2bfloat16(v2 - __bfloat162float(h2));
        g_Wv[2][o] = h2; g_Wv[2][o + 512] = l2; g_Wv[2][o + 1024] = h2;
    }
    if (idx < G4) {
        int p = idx;
        int s = ((p & 3) << 9) | (p >> 2);
        g_bias[0][p] = encBih[s] + encBhh[s];
        float db = decBih[s] + decBhh[s];
        g_bias[1][p] = db;
        g_bias[2][p] = db + outB[0] * decWih[s];       // fold outB feedback
#pragma unroll
        for (int j = 0; j < IN_SZ; j++) g_WihP[p * IN_SZ + j] = encWih[s * IN_SZ + j];
    }
}

__global__ void init_kernel() {
    int i = blockIdx.x * blockDim.x + threadIdx.x;
    int stride = gridDim.x * blockDim.x;
    uint32_t* a0 = reinterpret_cast<uint32_t*>(g_A[0]);
    for (int idx = i; idx < B_SZ * KV / 2; idx += stride) a0[idx] = 0u;
    for (int idx = i; idx < B_SZ * H_SZ; idx += stride) g_Cst[idx] = 0.f;
}

// ---------------- one LSTM time step ----------------
// C[128x128 tile] = A_virt[1024x1536] x B_virt[2048x1536]^T, then gate math locally.
// grid (16, 8): blockIdx.x = N-tile (128 permuted gate cols = 32 units), blockIdx.y = M-tile
// 512 threads = 16 warps arranged 4m x 4n; warp tile 32x32.
__global__ void __launch_bounds__(512, 1)
step_kernel(int wsel, int pb, int t_x, int td,
            const float* __restrict__ x, const float* __restrict__ outW) {
    extern __shared__ char smem[];
    const uint32_t sb = smem_u32(smem);
    const int tid = threadIdx.x;
    const int n0 = blockIdx.x, m0 = blockIdx.y;
    const bool has_x = (t_x >= 0);

    // ---- epilogue constants into their own smem region ----
    float* sm_bias = (float*)(smem + SM_BIAS);
    float* sm_wih  = (float*)(smem + SM_WIH);
    float* sm_xs   = (float*)(smem + SM_XS);
    float* sm_outw = (float*)(smem + SM_OUTW);
    if (tid < 128) sm_bias[tid] = g_bias[wsel][n0 * 128 + tid];
    if (tid < 32)  sm_outw[tid] = outW[n0 * 32 + tid];
    if (has_x) {
        for (int i = tid; i < 128 * IN_SZ; i += 512) {
            sm_wih[i] = g_WihP[n0 * 128 * IN_SZ + i];
            int r = i >> 3, j = i & 7;
            sm_xs[r * 9 + j] = x[((size_t)(m0 * 128 + r) * S_SZ + t_x) * IN_SZ + j];
        }
    }

    const __nv_bfloat16* __restrict__ gA = g_A[pb] + (size_t)m0 * 128 * KV;
    const __nv_bfloat16* __restrict__ gB = g_Wv[wsel] + (size_t)n0 * 128 * KV;

    // ---- stage loader: global -> XOR-swizzled smem via cp.async (512 threads) ----
    auto load_stage = [&](int kc, int slot) {
        const uint32_t stA = sb + slot * STAGE_BYTES;
        const uint32_t stB = stA + 16384;
        const int c16 = tid & 7;
        const int rb = tid >> 3;          // 0..63
#pragma unroll
        for (int it = 0; it < 2; it++) {
            int r = rb + it * 64;
            uint32_t so = (uint32_t)(r * 128 + ((c16 ^ (r & 7)) << 4));
            cp16(stA + so, gA + (size_t)r * KV + kc * 64 + c16 * 8);
            cp16(stB + so, gB + (size_t)r * KV + kc * 64 + c16 * 8);
        }
    };

    load_stage(0, 0); CP_COMMIT();
    load_stage(1, 1); CP_COMMIT();
    load_stage(2, 2); CP_COMMIT();

    const int lane = tid & 31, w = tid >> 5;
    const int wm = w & 3, wn = w >> 2;        // 4m x 4n warps, warp tile 32m x 32n
    const int lrow = lane & 15, lhalf = lane >> 4;

    float acc[2][4][4];
#pragma unroll
    for (int a = 0; a < 2; a++)
#pragma unroll
        for (int b = 0; b < 4; b++)
#pragma unroll
            for (int c = 0; c < 4; c++) acc[a][b][c] = 0.f;

    // ---- mainloop: 24 chunks of K=64, 4-stage cp.async pipeline ----
    for (int kc = 0; kc < NCHUNK; kc++) {
        CP_WAIT2();
        __syncthreads();
        const uint32_t stA = sb + (kc & 3) * STAGE_BYTES;
        const uint32_t stB = stA + 16384;
#pragma unroll
        for (int kk = 0; kk < 4; kk++) {
            const int c16 = 2 * kk + lhalf;
            uint32_t af[2][4];
#pragma unroll
            for (int mt = 0; mt < 2; mt++) {
                int r = wm * 32 + mt * 16 + lrow;
                ldm4(af[mt][0], af[mt][1], af[mt][2], af[mt][3],
                     stA + r * 128 + ((c16 ^ (r & 7)) << 4));
            }
            uint32_t bfr[4][2];
#pragma unroll
            for (int nb = 0; nb < 2; nb++) {
                int r = wn * 32 + nb * 16 + lrow;
                uint32_t r0, r1, r2, r3;
                ldm4(r0, r1, r2, r3, stB + r * 128 + ((c16 ^ (r & 7)) << 4));
                bfr[nb * 2 + 0][0] = r0; bfr[nb * 2 + 0][1] = r2;
                bfr[nb * 2 + 1][0] = r1; bfr[nb * 2 + 1][1] = r3;
            }
#pragma unroll
            for (int mt = 0; mt < 2; mt++)
#pragma unroll
                for (int nt = 0; nt < 4; nt++)
                    mma16816(acc[mt][nt], af[mt], bfr[nt]);
        }
        if (kc + 3 < NCHUNK) load_stage(kc + 3, (kc + 3) & 3);
        CP_COMMIT();   // unconditional: keeps wait_group 2 semantics at the tail
    }

    // ---- spill accum tile to smem (reuse stage region), stride 132 for aligned float4 ----
    __syncthreads();
    float* Cs = reinterpret_cast<float*>(smem);
#pragma unroll
    for (int mt = 0; mt < 2; mt++) {
#pragma unroll
        for (int nt = 0; nt < 4; nt++) {
            int r = wm * 32 + mt * 16 + (lane >> 2);
            int c = wn * 32 + nt * 8 + 2 * (lane & 3);
            Cs[r * 132 + c]           = acc[mt][nt][0];
            Cs[r * 132 + c + 1]       = acc[mt][nt][1];
            Cs[(r + 8) * 132 + c]     = acc[mt][nt][2];
            Cs[(r + 8) * 132 + c + 1] = acc[mt][nt][3];
        }
    }
    __syncthreads();

    // ---- gate pass: lane = local unit (cols 4u..4u+3 = i,f,g,o), 16 warps x 8 rows ----
    const int u = lane;
    const int ug = n0 * 32 + u;
    float wih[4][8];
    if (has_x) {
#pragma unroll
        for (int q = 0; q < 4; q++)
#pragma unroll
            for (int k = 0; k < 8; k++) wih[q][k] = sm_wih[(4 * u + q) * 8 + k];
    }
    const float b_i = sm_bias[4 * u], b_f = sm_bias[4 * u + 1];
    const float b_g = sm_bias[4 * u + 2], b_o = sm_bias[4 * u + 3];
    const float ow = sm_outw[u];
    __nv_bfloat16* __restrict__ hout = g_A[pb ^ 1];
    const int wrow = tid >> 5;

#pragma unroll 4
    for (int i = 0; i < 8; i++) {
        int r = wrow + i * 16;
        int grow = m0 * 128 + r;
        const float4 g4v = *reinterpret_cast<const float4*>(&Cs[r * 132 + 4 * u]);
        float gi = g4v.x + b_i, gf = g4v.y + b_f, gg = g4v.z + b_g, go = g4v.w + b_o;
        if (has_x) {
#pragma unroll
            for (int k = 0; k < 8; k++) {
                float xv = sm_xs[r * 9 + k];
                gi += xv * wih[0][k]; gf += xv * wih[1][k];
                gg += xv * wih[2][k]; go += xv * wih[3][k];
            }
        }
        float iv = 1.f / (1.f + expf(-gi));
        float fv = 1.f / (1.f + expf(-gf));
        float gv = tanhf(gg);
        float ov = 1.f / (1.f + expf(-go));
        size_t ci = (size_t)grow * H_SZ + ug;
        float cn = fv * g_Cst[ci] + iv * gv;
        g_Cst[ci] = cn;
        float hv = ov * tanhf(cn);
        __nv_bfloat16 hh = __float2bfloat16(hv);
        __nv_bfloat16 hl = __float2bfloat16(hv - __bfloat162float(hh));
        __nv_bfloat16* rowp = hout + (size_t)grow * KV;
        rowp[ug] = hh; rowp[512 + ug] = hh; rowp[1024 + ug] = hl;   // [Ah | Ah | Al]
        if (td >= 0) {
            float p = hv * ow;
#pragma unroll
            for (int s = 16; s > 0; s >>= 1) p += __shfl_xor_sync(0xFFFFFFFFu, p, s);
            if (lane == 0) g_predP[td][n0][grow] = p;   // deterministic partial
        }
    }
}

// ---------------- output: out[b][f] = outB + sum_n predP[f][n][b] ----------------
__global__ void out_kernel(float* __restrict__ out, const float* __restrict__ outB) {
    int i = blockIdx.x * blockDim.x + threadIdx.x;
    if (i < B_SZ * F_SZ) {
        int b = i / F_SZ, f = i % F_SZ;
        float s = outB[0];
#pragma unroll
        for (int n = 0; n < NCTA_N; n++) s += g_predP[f][n][b];
        out[i] = s;
    }
}

// ---------------- launch ----------------
extern "C" void kernel_launch(void* const* d_in, const int* in_sizes, int n_in,
                              void* d_out, int out_size) {
    const float* x      = (const float*)d_in[0];
    const float* encWih = (const float*)d_in[1];
    const float* encWhh = (const float*)d_in[2];
    const float* encBih = (const float*)d_in[3];
    const float* encBhh = (const float*)d_in[4];
    const float* decWih = (const float*)d_in[5];
    const float* decWhh = (const float*)d_in[6];
    const float* decBih = (const float*)d_in[7];
    const float* decBhh = (const float*)d_in[8];
    const float* outW   = (const float*)d_in[9];
    const float* outB   = (const float*)d_in[10];

    cudaFuncSetAttribute(step_kernel, cudaFuncAttributeMaxDynamicSharedMemorySize, SMEM_TOTAL);

    init_kernel<<<512, 256>>>();
    prep_kernel<<<(G4 * H_SZ + 255) / 256, 256>>>(encWhh, decWhh, decWih, outW,
                                                  encBih, encBhh, decBih, decBhh, outB, encWih);
    dim3 grid(NCTA_N, NCTA_M);
    // encoder: 256 steps with x-term, weight set 0
    for (int t = 0; t < S_SZ; t++)
        step_kernel<<<grid, 512, SMEM_TOTAL>>>(0, t & 1, t, -1, x, outW);
    // decoder step 0: y0 = 0 -> plain dec weights (set 1)
    step_kernel<<<grid, 512, SMEM_TOTAL>>>(1, S_SZ & 1, -1, 0, x, outW);
    // decoder steps 1..95: feedback folded into weights (set 2)
    for (int t = 1; t < F_SZ; t++)
        step_kernel<<<grid, 512, SMEM_TOTAL>>>(2, (S_SZ + t) & 1, -1, t, x, outW);

    out_kernel<<<(B_SZ * F_SZ + 255) / 256, 256>>>((float*)d_out, outB);
}

// round 8
// speedup vs baseline: 1.3685x; 1.2574x over previous
#include <cuda_runtime.h>
#include <cuda_fp16.h>
#include <cuda_bf16.h>
#include <cstdint>

// ---------------- problem dims ----------------
#define B_SZ   1024
#define S_SZ   256
#define IN_SZ  8
#define H_SZ   512
#define F_SZ   96
#define G4     2048          // 4*H
#define KV     1024          // virtual K: [Ah | Ah] x [Wh | Wl]  (fp16 2-term split)
#define NCHUNK 16            // KV / 64
#define NCTA_N 16
#define NCTA_M 8

// ---------------- shared memory layout ----------------
// 4 stages x (A 16 KB + B 16 KB); epilogue reuses stage region as C (128x132 f32)
#define STAGE_BYTES 32768
#define SM_BIAS   131072
#define SM_WIH    131584
#define SM_XS     135680
#define SM_OUTW   140288
#define SMEM_TOTAL 140416

// ---------------- static device scratch (no runtime alloc) ----------------
__device__ __align__(1024) __half g_Wv[3][(size_t)G4 * KV];   // enc / dec0 / dec-folded
__device__ __align__(1024) __half g_A[2][(size_t)B_SZ * KV];  // ping-pong A_virt
__device__ __align__(1024) float g_Cst[B_SZ * H_SZ];          // cell state fp32
__device__ float g_bias[3][G4];                               // permuted fused biases
__device__ float g_WihP[G4 * IN_SZ];                          // permuted enc_Wih
__device__ float g_predP[F_SZ][NCTA_N][B_SZ];                 // per-nCTA pred partials

// ---------------- helpers ----------------
__device__ __forceinline__ uint32_t smem_u32(const void* p) {
    uint32_t a;
    asm("{ .reg .u64 t; cvta.to.shared.u64 t, %1; cvt.u32.u64 %0, t; }" : "=r"(a) : "l"(p));
    return a;
}
__device__ __forceinline__ void cp16(uint32_t saddr, const void* gptr) {
    asm volatile("cp.async.cg.shared.global [%0], [%1], 16;"
                 :: "r"(saddr), "l"(__cvta_generic_to_global(gptr)) : "memory");
}
#define CP_COMMIT() asm volatile("cp.async.commit_group;" ::: "memory")
#define CP_WAIT2()  asm volatile("cp.async.wait_group 2;" ::: "memory")

__device__ __forceinline__ void ldm4(uint32_t& r0, uint32_t& r1, uint32_t& r2, uint32_t& r3,
                                     uint32_t addr) {
    asm volatile("ldmatrix.sync.aligned.m8n8.x4.shared.b16 {%0,%1,%2,%3}, [%4];"
                 : "=r"(r0), "=r"(r1), "=r"(r2), "=r"(r3) : "r"(addr));
}
__device__ __forceinline__ void mma16816(float* c, const uint32_t* a, const uint32_t* b) {
    asm volatile(
        "mma.sync.aligned.m16n8k16.row.col.f32.f16.f16.f32 "
        "{%0,%1,%2,%3}, {%4,%5,%6,%7}, {%8,%9}, {%0,%1,%2,%3};"
        : "+f"(c[0]), "+f"(c[1]), "+f"(c[2]), "+f"(c[3])
        : "r"(a[0]), "r"(a[1]), "r"(a[2]), "r"(a[3]), "r"(b[0]), "r"(b[1]));
}

// ---------------- prep: permute + fp16 hi/lo split weights, fold decoder feedback ----------------
// permuted col p = 4u + gate  <-  source row s = gate*512 + u  (PyTorch gate order i,f,g,o)
__global__ void prep_kernel(const float* __restrict__ encWhh, const float* __restrict__ decWhh,
                            const float* __restrict__ decWih, const float* __restrict__ outW,
                            const float* __restrict__ encBih, const float* __restrict__ encBhh,
                            const float* __restrict__ decBih, const float* __restrict__ decBhh,
                            const float* __restrict__ outB,   const float* __restrict__ encWih) {
    int idx = blockIdx.x * blockDim.x + threadIdx.x;
    if (idx < G4 * H_SZ) {
        int p = idx >> 9;
        int k = idx & 511;
        int s = ((p & 3) << 9) | (p >> 2);
        size_t o = (size_t)p * KV + k;

        float v0 = encWhh[s * H_SZ + k];
        __half h0 = __float2half_rn(v0);
        g_Wv[0][o] = h0; g_Wv[0][o + 512] = __float2half_rn(v0 - __half2float(h0));

        float v1 = decWhh[s * H_SZ + k];
        __half h1 = __float2half_rn(v1);
        g_Wv[1][o] = h1; g_Wv[1][o + 512] = __float2half_rn(v1 - __half2float(h1));

        float v2 = v1 + decWih[s] * outW[k];           // fold y-feedback into Whh
        __half h2 = __float2half_rn(v2);
        g_Wv[2][o] = h2; g_Wv[2][o + 512] = __float2half_rn(v2 - __half2float(h2));
    }
    if (idx < G4) {
        int p = idx;
        int s = ((p & 3) << 9) | (p >> 2);
        g_bias[0][p] = encBih[s] + encBhh[s];
        float db = decBih[s] + decBhh[s];
        g_bias[1][p] = db;
        g_bias[2][p] = db + outB[0] * decWih[s];       // fold outB feedback
#pragma unroll
        for (int j = 0; j < IN_SZ; j++) g_WihP[p * IN_SZ + j] = encWih[s * IN_SZ + j];
    }
}

__global__ void init_kernel() {
    int i = blockIdx.x * blockDim.x + threadIdx.x;
    int stride = gridDim.x * blockDim.x;
    uint32_t* a0 = reinterpret_cast<uint32_t*>(g_A[0]);
    for (int idx = i; idx < B_SZ * KV / 2; idx += stride) a0[idx] = 0u;
    for (int idx = i; idx < B_SZ * H_SZ; idx += stride) g_Cst[idx] = 0.f;
}

// ---------------- one LSTM time step ----------------
// C[128x128 tile] = A_virt[1024x1024] x B_virt[2048x1024]^T, then gate math locally.
// grid (16, 8): blockIdx.x = N-tile (128 permuted gate cols = 32 units), blockIdx.y = M-tile.
// 512 threads = 16 warps arranged 2m x 4n x 2k; warp tile 64m x 32n, K split in halves
// of each 64-K chunk (reduced at spill time through smem).
__global__ void __launch_bounds__(512, 1)
step_kernel(int wsel, int pb, int t_x, int td,
            const float* __restrict__ x, const float* __restrict__ outW) {
    extern __shared__ char smem[];
    const uint32_t sb = smem_u32(smem);
    const int tid = threadIdx.x;
    const int n0 = blockIdx.x, m0 = blockIdx.y;
    const bool has_x = (t_x >= 0);

    // ---- epilogue constants into their own smem region ----
    float* sm_bias = (float*)(smem + SM_BIAS);
    float* sm_wih  = (float*)(smem + SM_WIH);
    float* sm_xs   = (float*)(smem + SM_XS);
    float* sm_outw = (float*)(smem + SM_OUTW);
    if (tid < 128) sm_bias[tid] = g_bias[wsel][n0 * 128 + tid];
    if (tid < 32)  sm_outw[tid] = outW[n0 * 32 + tid];
    if (has_x) {
        for (int i = tid; i < 128 * IN_SZ; i += 512) {
            sm_wih[i] = g_WihP[n0 * 128 * IN_SZ + i];
            int r = i >> 3, j = i & 7;
            sm_xs[r * 9 + j] = x[((size_t)(m0 * 128 + r) * S_SZ + t_x) * IN_SZ + j];
        }
    }

    const __half* __restrict__ gA = g_A[pb] + (size_t)m0 * 128 * KV;
    const __half* __restrict__ gB = g_Wv[wsel] + (size_t)n0 * 128 * KV;

    // ---- stage loader: global -> XOR-swizzled smem via cp.async (512 threads) ----
    auto load_stage = [&](int kc, int slot) {
        const uint32_t stA = sb + slot * STAGE_BYTES;
        const uint32_t stB = stA + 16384;
        const int c16 = tid & 7;
        const int rb = tid >> 3;          // 0..63
#pragma unroll
        for (int it = 0; it < 2; it++) {
            int r = rb + it * 64;
            uint32_t so = (uint32_t)(r * 128 + ((c16 ^ (r & 7)) << 4));
            cp16(stA + so, gA + (size_t)r * KV + kc * 64 + c16 * 8);
            cp16(stB + so, gB + (size_t)r * KV + kc * 64 + c16 * 8);
        }
    };

    load_stage(0, 0); CP_COMMIT();
    load_stage(1, 1); CP_COMMIT();
    load_stage(2, 2); CP_COMMIT();

    const int lane = tid & 31, w = tid >> 5;
    const int wk = w & 1;                 // K-half of each chunk
    const int wn = (w >> 1) & 3;          // 4 n-columns of 32
    const int wm = w >> 3;                // 2 m-rows of 64
    const int lrow = lane & 15, lhalf = lane >> 4;

    float acc[4][4][4];
#pragma unroll
    for (int a = 0; a < 4; a++)
#pragma unroll
        for (int b = 0; b < 4; b++)
#pragma unroll
            for (int c = 0; c < 4; c++) acc[a][b][c] = 0.f;

    // ---- mainloop: 16 chunks of K=64, 4-stage cp.async pipeline, warp-level K-split ----
    for (int kc = 0; kc < NCHUNK; kc++) {
        CP_WAIT2();
        __syncthreads();
        const uint32_t stA = sb + (kc & 3) * STAGE_BYTES;
        const uint32_t stB = stA + 16384;
#pragma unroll
        for (int j = 0; j < 2; j++) {
            const int c16 = 2 * (wk * 2 + j) + lhalf;
            uint32_t af[4][4];
#pragma unroll
            for (int mt = 0; mt < 4; mt++) {
                int r = wm * 64 + mt * 16 + lrow;
                ldm4(af[mt][0], af[mt][1], af[mt][2], af[mt][3],
                     stA + r * 128 + ((c16 ^ (r & 7)) << 4));
            }
            uint32_t bfr[4][2];
#pragma unroll
            for (int nb = 0; nb < 2; nb++) {
                int r = wn * 32 + nb * 16 + lrow;
                uint32_t r0, r1, r2, r3;
                ldm4(r0, r1, r2, r3, stB + r * 128 + ((c16 ^ (r & 7)) << 4));
                bfr[nb * 2 + 0][0] = r0; bfr[nb * 2 + 0][1] = r2;
                bfr[nb * 2 + 1][0] = r1; bfr[nb * 2 + 1][1] = r3;
            }
#pragma unroll
            for (int mt = 0; mt < 4; mt++)
#pragma unroll
                for (int nt = 0; nt < 4; nt++)
                    mma16816(acc[mt][nt], af[mt], bfr[nt]);
        }
        if (kc + 3 < NCHUNK) load_stage(kc + 3, (kc + 3) & 3);
        CP_COMMIT();   // unconditional: keeps wait_group 2 semantics at the tail
    }

    // ---- spill + K-half reduction into smem C tile (stride 132 for aligned float4) ----
    __syncthreads();
    float* Cs = reinterpret_cast<float*>(smem);
    if (wk == 0) {
#pragma unroll
        for (int mt = 0; mt < 4; mt++) {
#pragma unroll
            for (int nt = 0; nt < 4; nt++) {
                int r = wm * 64 + mt * 16 + (lane >> 2);
                int c = wn * 32 + nt * 8 + 2 * (lane & 3);
                Cs[r * 132 + c]           = acc[mt][nt][0];
                Cs[r * 132 + c + 1]       = acc[mt][nt][1];
                Cs[(r + 8) * 132 + c]     = acc[mt][nt][2];
                Cs[(r + 8) * 132 + c + 1] = acc[mt][nt][3];
            }
        }
    }
    __syncthreads();
    if (wk == 1) {
#pragma unroll
        for (int mt = 0; mt < 4; mt++) {
#pragma unroll
            for (int nt = 0; nt < 4; nt++) {
                int r = wm * 64 + mt * 16 + (lane >> 2);
                int c = wn * 32 + nt * 8 + 2 * (lane & 3);
                float2* p0 = reinterpret_cast<float2*>(&Cs[r * 132 + c]);
                float2 v0 = *p0; v0.x += acc[mt][nt][0]; v0.y += acc[mt][nt][1]; *p0 = v0;
                float2* p1 = reinterpret_cast<float2*>(&Cs[(r + 8) * 132 + c]);
                float2 v1 = *p1; v1.x += acc[mt][nt][2]; v1.y += acc[mt][nt][3]; *p1 = v1;
            }
        }
    }
    __syncthreads();

    // ---- gate pass: lane = local unit (cols 4u..4u+3 = i,f,g,o), 16 warps x 8 rows ----
    const int u = lane;
    const int ug = n0 * 32 + u;
    float wih[4][8];
    if (has_x) {
#pragma unroll
        for (int q = 0; q < 4; q++)
#pragma unroll
            for (int k = 0; k < 8; k++) wih[q][k] = sm_wih[(4 * u + q) * 8 + k];
    }
    const float b_i = sm_bias[4 * u], b_f = sm_bias[4 * u + 1];
    const float b_g = sm_bias[4 * u + 2], b_o = sm_bias[4 * u + 3];
    const float ow = sm_outw[u];
    __half* __restrict__ hout = g_A[pb ^ 1];
    const int wrow = tid >> 5;

#pragma unroll 4
    for (int i = 0; i < 8; i++) {
        int r = wrow + i * 16;
        int grow = m0 * 128 + r;
        const float4 g4v = *reinterpret_cast<const float4*>(&Cs[r * 132 + 4 * u]);
        float gi = g4v.x + b_i, gf = g4v.y + b_f, gg = g4v.z + b_g, go = g4v.w + b_o;
        if (has_x) {
#pragma unroll
            for (int k = 0; k < 8; k++) {
                float xv = sm_xs[r * 9 + k];
                gi += xv * wih[0][k]; gf += xv * wih[1][k];
                gg += xv * wih[2][k]; go += xv * wih[3][k];
            }
        }
        float iv = 1.f / (1.f + expf(-gi));
        float fv = 1.f / (1.f + expf(-gf));
        float gv = tanhf(gg);
        float ov = 1.f / (1.f + expf(-go));
        size_t ci = (size_t)grow * H_SZ + ug;
        float cn = fv * g_Cst[ci] + iv * gv;
        g_Cst[ci] = cn;
        float hv = ov * tanhf(cn);
        __half hh = __float2half_rn(hv);
        __half* rowp = hout + (size_t)grow * KV;
        rowp[ug] = hh; rowp[512 + ug] = hh;            // A_virt = [Ah | Ah]
        if (td >= 0) {
            float p = hv * ow;
#pragma unroll
            for (int s = 16; s > 0; s >>= 1) p += __shfl_xor_sync(0xFFFFFFFFu, p, s);
            if (lane == 0) g_predP[td][n0][grow] = p;   // deterministic partial
        }
    }
}

// ---------------- output: out[b][f] = outB + sum_n predP[f][n][b] ----------------
__global__ void out_kernel(float* __restrict__ out, const float* __restrict__ outB) {
    int i = blockIdx.x * blockDim.x + threadIdx.x;
    if (i < B_SZ * F_SZ) {
        int b = i / F_SZ, f = i % F_SZ;
        float s = outB[0];
#pragma unroll
        for (int n = 0; n < NCTA_N; n++) s += g_predP[f][n][b];
        out[i] = s;
    }
}

// ---------------- launch ----------------
extern "C" void kernel_launch(void* const* d_in, const int* in_sizes, int n_in,
                              void* d_out, int out_size) {
    const float* x      = (const float*)d_in[0];
    const float* encWih = (const float*)d_in[1];
    const float* encWhh = (const float*)d_in[2];
    const float* encBih = (const float*)d_in[3];
    const float* encBhh = (const float*)d_in[4];
    const float* decWih = (const float*)d_in[5];
    const float* decWhh = (const float*)d_in[6];
    const float* decBih = (const float*)d_in[7];
    const float* decBhh = (const float*)d_in[8];
    const float* outW   = (const float*)d_in[9];
    const float* outB   = (const float*)d_in[10];

    cudaFuncSetAttribute(step_kernel, cudaFuncAttributeMaxDynamicSharedMemorySize, SMEM_TOTAL);

    init_kernel<<<512, 256>>>();
    prep_kernel<<<(G4 * H_SZ + 255) / 256, 256>>>(encWhh, decWhh, decWih, outW,
                                                  encBih, encBhh, decBih, decBhh, outB, encWih);
    dim3 grid(NCTA_N, NCTA_M);
    // encoder: 256 steps with x-term, weight set 0
    for (int t = 0; t < S_SZ; t++)
        step_kernel<<<grid, 512, SMEM_TOTAL>>>(0, t & 1, t, -1, x, outW);
    // decoder step 0: y0 = 0 -> plain dec weights (set 1)
    step_kernel<<<grid, 512, SMEM_TOTAL>>>(1, S_SZ & 1, -1, 0, x, outW);
    // decoder steps 1..95: feedback folded into weights (set 2)
    for (int t = 1; t < F_SZ; t++)
        step_kernel<<<grid, 512, SMEM_TOTAL>>>(2, (S_SZ + t) & 1, -1, t, x, outW);

    out_kernel<<<(B_SZ * F_SZ + 255) / 256, 256>>>((float*)d_out, outB);
}